// round 1
// baseline (speedup 1.0000x reference)
#include <cuda_runtime.h>
#include <cstdint>

// Problem constants
#define T_TOK 4096      // total tokens (B*S)
#define DDIM  4096      // D_IN == D_OUT
#define NE    8         // experts
#define TOPK  2

// GEMM tile config
#define BM 128
#define BN 128
#define BK 32
#define NSTAGE 3
#define ALD 36          // BK + 4 pad (ld in floats); 36*4B=144B, 16B aligned rows
#define GEMM_THREADS 256

// -------- device-global scratch (no allocation allowed) --------
__device__ int   g_cnt[NE];
__device__ float g_importance[NE];
__device__ int   g_tok[NE * T_TOK];
__device__ float g_scale[NE * T_TOK];

// ---------------------------------------------------------------
__global__ void reset_kernel() {
    int i = threadIdx.x;
    if (i < NE) { g_cnt[i] = 0; g_importance[i] = 0.f; }
}

// One block (128 threads) per token: logits = tanh(x @ gw1^T) @ gw2^T, top-2,
// softmax, append to per-expert lists.
__global__ void gate_kernel(const float* __restrict__ x,
                            const float* __restrict__ gw1,
                            const float* __restrict__ gw2) {
    int t = blockIdx.x;
    const float* xr = x + (size_t)t * DDIM;

    float acc[NE];
#pragma unroll
    for (int e = 0; e < NE; e++) acc[e] = 0.f;

    for (int i = threadIdx.x; i < DDIM; i += 128) {
        float xv = xr[i];
#pragma unroll
        for (int e = 0; e < NE; e++) acc[e] += xv * gw1[e * DDIM + i];
    }
    // warp reduce each acc
#pragma unroll
    for (int e = 0; e < NE; e++) {
#pragma unroll
        for (int o = 16; o > 0; o >>= 1)
            acc[e] += __shfl_xor_sync(0xffffffffu, acc[e], o);
    }
    __shared__ float part[NE][4];
    __shared__ float hs[NE];
    __shared__ float ls[NE];
    int lane = threadIdx.x & 31, warp = threadIdx.x >> 5;
    if (lane == 0) {
#pragma unroll
        for (int e = 0; e < NE; e++) part[e][warp] = acc[e];
    }
    __syncthreads();
    if (threadIdx.x < NE) {
        int e = threadIdx.x;
        hs[e] = tanhf(part[e][0] + part[e][1] + part[e][2] + part[e][3]);
    }
    __syncthreads();
    if (threadIdx.x < NE) {
        int j = threadIdx.x;
        float l = 0.f;
#pragma unroll
        for (int e = 0; e < NE; e++) l += gw2[j * NE + e] * hs[e];
        ls[j] = l;
    }
    __syncthreads();
    if (threadIdx.x == 0) {
        // top-2 (first-index tie-break like jax top_k)
        int i0 = 0; float v0 = ls[0];
        for (int j = 1; j < NE; j++) if (ls[j] > v0) { v0 = ls[j]; i0 = j; }
        int i1 = -1; float v1 = -3.4e38f;
        for (int j = 0; j < NE; j++) if (j != i0 && ls[j] > v1) { v1 = ls[j]; i1 = j; }
        float z  = expf(v1 - v0);           // <= 1
        float s0 = 1.f / (1.f + z);
        float s1 = z * s0;
        int p0 = atomicAdd(&g_cnt[i0], 1);
        g_tok[i0 * T_TOK + p0]   = t;
        g_scale[i0 * T_TOK + p0] = s0;
        int p1 = atomicAdd(&g_cnt[i1], 1);
        g_tok[i1 * T_TOK + p1]   = t;
        g_scale[i1 * T_TOK + p1] = s1;
        atomicAdd(&g_importance[i0], s0);
        atomicAdd(&g_importance[i1], s1);
    }
}

// cv^2 with unbiased var, loss = 0.01 * (cv2(importance) + cv2(load))
__global__ void loss_kernel(float* __restrict__ out) {
    float v[NE], w[NE];
    float m1 = 0.f, m2 = 0.f;
#pragma unroll
    for (int e = 0; e < NE; e++) {
        v[e] = g_importance[e];
        w[e] = (float)g_cnt[e];
        m1 += v[e]; m2 += w[e];
    }
    m1 *= (1.f / NE); m2 *= (1.f / NE);
    float var1 = 0.f, var2 = 0.f;
#pragma unroll
    for (int e = 0; e < NE; e++) {
        float d1 = v[e] - m1; var1 += d1 * d1;
        float d2 = w[e] - m2; var2 += d2 * d2;
    }
    var1 *= (1.f / (NE - 1)); var2 *= (1.f / (NE - 1));
    out[0] = 0.01f * (var1 / (m1 * m1 + 1e-10f) + var2 / (m2 * m2 + 1e-10f));
}

// ---------------------------------------------------------------
__device__ __forceinline__ uint32_t f2tf(float f) {
    uint32_t r;
    asm volatile("cvt.rna.tf32.f32 %0, %1;\n" : "=r"(r) : "f"(f));
    return r;
}
__device__ __forceinline__ void mma_tf32(float* c, const uint32_t* a, const uint32_t* b) {
    asm volatile(
        "mma.sync.aligned.m16n8k8.row.col.f32.tf32.tf32.f32 "
        "{%0,%1,%2,%3}, {%4,%5,%6,%7}, {%8,%9}, {%0,%1,%2,%3};\n"
        : "+f"(c[0]), "+f"(c[1]), "+f"(c[2]), "+f"(c[3])
        : "r"(a[0]), "r"(a[1]), "r"(a[2]), "r"(a[3]), "r"(b[0]), "r"(b[1]));
}
__device__ __forceinline__ void cp_async16(void* smem_dst, const void* gsrc) {
    uint32_t s = (uint32_t)__cvta_generic_to_shared(smem_dst);
    asm volatile("cp.async.cg.shared.global [%0], [%1], 16;\n" :: "r"(s), "l"(gsrc) : "memory");
}

// Grouped expert GEMM: C[m,n] = sum_k x[tok[m],k] * W_e[n,k]; epilogue
// y[tok[m], n] += scale[m] * (C + bias_e[n]) via atomicAdd (2 commutative adds).
__global__ void __launch_bounds__(GEMM_THREADS, 2)
moe_gemm(const float* __restrict__ x, const float* __restrict__ W,
         const float* __restrict__ bias, float* __restrict__ y) {
    int e   = blockIdx.z;
    int cnt = g_cnt[e];
    int m0  = blockIdx.x * BM;
    if (m0 >= cnt) return;
    int n0  = blockIdx.y * BN;

    extern __shared__ float smem[];
    float* As     = smem;                                   // NSTAGE*BM*ALD
    float* Bs     = As + NSTAGE * BM * ALD;                 // NSTAGE*BN*ALD
    float* sBias  = Bs + NSTAGE * BN * ALD;                 // BN
    float* sScale = sBias + BN;                             // BM
    int*   sTok   = (int*)(sScale + BM);                    // BM

    int tid = threadIdx.x;
    if (tid < BM) {
        int m = m0 + tid;
        bool valid = m < cnt;
        sTok[tid]   = valid ? g_tok[e * T_TOK + m]   : 0;
        sScale[tid] = valid ? g_scale[e * T_TOK + m] : 0.f;
    } else {
        int n = tid - BM;   // 0..127
        sBias[n] = bias[e * DDIM + n0 + n];
    }
    __syncthreads();

    const float* Wb = W + ((size_t)e << 24) + (size_t)n0 * DDIM;

    auto load_stage = [&](int stage, int kt) {
        int kk = kt * BK;
        float* as = As + stage * (BM * ALD);
        float* bs = Bs + stage * (BN * ALD);
#pragma unroll
        for (int it = 0; it < 4; it++) {
            int idx = tid + it * GEMM_THREADS;      // 0..1023
            int r = idx >> 3, c = idx & 7;
            cp_async16(as + r * ALD + c * 4, x + (size_t)sTok[r] * DDIM + kk + c * 4);
        }
#pragma unroll
        for (int it = 0; it < 4; it++) {
            int idx = tid + it * GEMM_THREADS;
            int r = idx >> 3, c = idx & 7;
            cp_async16(bs + r * ALD + c * 4, Wb + (size_t)r * DDIM + kk + c * 4);
        }
        asm volatile("cp.async.commit_group;\n" ::: "memory");
    };

    const int KT = DDIM / BK;  // 128
    load_stage(0, 0);
    load_stage(1, 1);

    int warp = tid >> 5;
    int wm   = warp & 3;        // 4 warps along M -> 32 rows each
    int wn   = warp >> 2;       // 2 warps along N -> 64 cols each
    int lane = tid & 31;
    int gid  = lane >> 2;       // 0..7
    int tg   = lane & 3;        // 0..3

    float c[2][8][4];
#pragma unroll
    for (int mi = 0; mi < 2; mi++)
#pragma unroll
        for (int ni = 0; ni < 8; ni++)
#pragma unroll
            for (int j = 0; j < 4; j++) c[mi][ni][j] = 0.f;

    for (int i = 0; i < KT; i++) {
        if (i < KT - 1) {
            asm volatile("cp.async.wait_group 1;\n" ::: "memory");
        } else {
            asm volatile("cp.async.wait_group 0;\n" ::: "memory");
        }
        __syncthreads();
        if (i + 2 < KT) load_stage((i + 2) % NSTAGE, i + 2);

        const float* as = As + (i % NSTAGE) * (BM * ALD) + (wm * 32) * ALD;
        const float* bs = Bs + (i % NSTAGE) * (BN * ALD) + (wn * 64) * ALD;

#pragma unroll
        for (int ks = 0; ks < BK / 8; ks++) {
            uint32_t a[2][4], b[8][2];
#pragma unroll
            for (int mi = 0; mi < 2; mi++) {
                const float* ap = as + (mi * 16 + gid) * ALD + ks * 8 + tg;
                a[mi][0] = f2tf(ap[0]);
                a[mi][1] = f2tf(ap[8 * ALD]);
                a[mi][2] = f2tf(ap[4]);
                a[mi][3] = f2tf(ap[8 * ALD + 4]);
            }
#pragma unroll
            for (int ni = 0; ni < 8; ni++) {
                const float* bp = bs + (ni * 8 + gid) * ALD + ks * 8 + tg;
                b[ni][0] = f2tf(bp[0]);
                b[ni][1] = f2tf(bp[4]);
            }
#pragma unroll
            for (int mi = 0; mi < 2; mi++)
#pragma unroll
                for (int ni = 0; ni < 8; ni++)
                    mma_tf32(c[mi][ni], a[mi], b[ni]);
        }
    }

    // epilogue: scatter-add
#pragma unroll
    for (int mi = 0; mi < 2; mi++) {
#pragma unroll
        for (int half = 0; half < 2; half++) {
            int r = wm * 32 + mi * 16 + gid + half * 8;
            if (m0 + r >= cnt) continue;
            int   tok = sTok[r];
            float sc  = sScale[r];
            float* yr = y + (size_t)tok * DDIM + n0;
#pragma unroll
            for (int ni = 0; ni < 8; ni++) {
                int col = wn * 64 + ni * 8 + tg * 2;
                float v0 = sc * (c[mi][ni][half * 2 + 0] + sBias[col]);
                float v1 = sc * (c[mi][ni][half * 2 + 1] + sBias[col + 1]);
                atomicAdd(&yr[col],     v0);
                atomicAdd(&yr[col + 1], v1);
            }
        }
    }
}

// ---------------------------------------------------------------
extern "C" void kernel_launch(void* const* d_in, const int* in_sizes, int n_in,
                              void* d_out, int out_size) {
    const float* x   = (const float*)d_in[0];
    const float* gw1 = (const float*)d_in[1];
    const float* gw2 = (const float*)d_in[2];
    const float* ew  = (const float*)d_in[3];
    const float* eb  = (const float*)d_in[4];
    float* out = (float*)d_out;

    // zero y (and loss slot); output poisoned 0xAA by harness
    cudaMemsetAsync(out, 0, (size_t)out_size * sizeof(float));

    reset_kernel<<<1, 32>>>();
    gate_kernel<<<T_TOK, 128>>>(x, gw1, gw2);
    if (out_size > T_TOK * DDIM) {
        loss_kernel<<<1, 1>>>(out + (size_t)T_TOK * DDIM);
    }

    int smem_bytes = (NSTAGE * (BM * ALD + BN * ALD) + BN + BM + BM) * (int)sizeof(float);
    cudaFuncSetAttribute(moe_gemm, cudaFuncAttributeMaxDynamicSharedMemorySize, smem_bytes);
    moe_gemm<<<dim3(T_TOK / BM, DDIM / BN, NE), GEMM_THREADS, smem_bytes>>>(x, ew, eb, out);
}